// round 4
// baseline (speedup 1.0000x reference)
#include <cuda_runtime.h>
#include <math.h>

#define BB 2
#define TT 2048
#define CC 1024
#define HH 16
#define HD 64

// Scratch (allocation-free rule: __device__ globals). All tf32 bit patterns.
__device__ unsigned g_xt[4096*1024];     // x converted
__device__ unsigned g_wt[3072*1024];     // [Wq;Wk;Wv] converted
__device__ unsigned g_wpt[1024*1024];    // Wp converted
__device__ unsigned g_q[BB*HH*TT*HD];
__device__ unsigned g_k[BB*HH*TT*HD];
__device__ unsigned g_v[BB*HH*TT*HD];
__device__ unsigned g_y[BB*TT*CC];

// ---------------------------------------------------------------------------
// helpers
// ---------------------------------------------------------------------------
__device__ __forceinline__ unsigned f2tf(float f) {
    unsigned u;
    asm("cvt.rna.tf32.f32 %0, %1;" : "=r"(u) : "f"(f));
    return u;
}

// D = A(16x8 tf32, row) * B(8x8 tf32, col) + D, fp32 accum
__device__ __forceinline__ void mma8(float* c, const unsigned* a, const unsigned* b) {
    asm volatile(
        "mma.sync.aligned.m16n8k8.row.col.f32.tf32.tf32.f32 "
        "{%0,%1,%2,%3},{%4,%5,%6,%7},{%8,%9},{%0,%1,%2,%3};"
        : "+f"(c[0]), "+f"(c[1]), "+f"(c[2]), "+f"(c[3])
        : "r"(a[0]), "r"(a[1]), "r"(a[2]), "r"(a[3]), "r"(b[0]), "r"(b[1]));
}

__device__ __forceinline__ void cp16(void* dst_smem, const void* src) {
    unsigned d = (unsigned)__cvta_generic_to_shared(dst_smem);
    asm volatile("cp.async.cg.shared.global [%0], [%1], 16;\n" :: "r"(d), "l"(src));
}
__device__ __forceinline__ void cp_commit() {
    asm volatile("cp.async.commit_group;\n");
}
__device__ __forceinline__ void cp_wait0() {
    asm volatile("cp.async.wait_group 0;\n");
}

// ---------------------------------------------------------------------------
// Pre-convert x and weights to tf32 bits. 2M float4 items.
// ---------------------------------------------------------------------------
__global__ __launch_bounds__(256) void convert_tf32(
    const float* __restrict__ x,
    const float* __restrict__ Wq, const float* __restrict__ Wk,
    const float* __restrict__ Wv, const float* __restrict__ Wp)
{
    int i = blockIdx.x * 256 + threadIdx.x;   // float4 index
    const float* src; unsigned* dst; int off;
    if (i < 1048576)      { src = x;  dst = g_xt;            off = i; }
    else if (i < 1310720) { src = Wq; dst = g_wt;            off = i - 1048576; }
    else if (i < 1572864) { src = Wk; dst = g_wt + 1048576;  off = i - 1310720; }
    else if (i < 1835008) { src = Wv; dst = g_wt + 2097152;  off = i - 1572864; }
    else                  { src = Wp; dst = g_wpt;           off = i - 1835008; }
    float4 v = ((const float4*)src)[off];
    uint4 o;
    o.x = f2tf(v.x); o.y = f2tf(v.y); o.z = f2tf(v.z); o.w = f2tf(v.w);
    ((uint4*)dst)[off] = o;
}

// ---------------------------------------------------------------------------
// QKV projection, double-buffered cp.async. Block 128x128, BK=16, 8 warps
// (2m x 4n), warp tile 64x32. Outputs tf32 bits in [B,H,T,HD].
// ---------------------------------------------------------------------------
__global__ __launch_bounds__(256) void qkv_gemm2(
    const float* __restrict__ bq, const float* __restrict__ bk,
    const float* __restrict__ bv)
{
    __shared__ unsigned As[2][128][20];
    __shared__ unsigned Bs[2][128][20];

    int tid = threadIdx.x;
    int lane = tid & 31, warp = tid >> 5;
    int g = lane >> 2, t4 = lane & 3;
    int wm = warp >> 2, wn = warp & 3;

    int mbase = blockIdx.y * 128;
    int cb = blockIdx.x * 128;
    int mat = cb >> 10;
    int nloc = cb & 1023;

    const float* bias = (mat == 0) ? bq : (mat == 1) ? bk : bv;
    unsigned* out     = (mat == 0) ? g_q : (mat == 1) ? g_k : g_v;

    const unsigned* Ag = g_xt + (size_t)mbase * CC;
    const unsigned* Bg = g_wt + (size_t)cb * CC;

    float acc[4][4][4];
    #pragma unroll
    for (int mt = 0; mt < 4; mt++)
        #pragma unroll
        for (int nt = 0; nt < 4; nt++)
            #pragma unroll
            for (int i = 0; i < 4; i++) acc[mt][nt][i] = 0.f;

    int lr = tid >> 2;            // 0..63
    int lc = (tid & 3) * 4;       // 0,4,8,12

    // prologue: stage 0
    #pragma unroll
    for (int i = 0; i < 2; i++) {
        int row = lr + i * 64;
        cp16(&As[0][row][lc], Ag + (size_t)row * CC + lc);
        cp16(&Bs[0][row][lc], Bg + (size_t)row * CC + lc);
    }
    cp_commit();

    int buf = 0;
    for (int it = 0; it < 64; it++) {
        cp_wait0();
        __syncthreads();
        if (it < 63) {
            int k0 = (it + 1) * 16;
            #pragma unroll
            for (int i = 0; i < 2; i++) {
                int row = lr + i * 64;
                cp16(&As[buf ^ 1][row][lc], Ag + (size_t)row * CC + k0 + lc);
                cp16(&Bs[buf ^ 1][row][lc], Bg + (size_t)row * CC + k0 + lc);
            }
            cp_commit();
        }

        #pragma unroll
        for (int k8 = 0; k8 < 2; k8++) {
            int kc = k8 * 8 + t4;
            unsigned a[4][4], b[4][2];
            #pragma unroll
            for (int mt = 0; mt < 4; mt++) {
                int mr = wm * 64 + mt * 16 + g;
                a[mt][0] = As[buf][mr][kc];
                a[mt][1] = As[buf][mr + 8][kc];
                a[mt][2] = As[buf][mr][kc + 4];
                a[mt][3] = As[buf][mr + 8][kc + 4];
            }
            #pragma unroll
            for (int nt = 0; nt < 4; nt++) {
                int nr = wn * 32 + nt * 8 + g;
                b[nt][0] = Bs[buf][nr][kc];
                b[nt][1] = Bs[buf][nr][kc + 4];
            }
            #pragma unroll
            for (int mt = 0; mt < 4; mt++)
                #pragma unroll
                for (int nt = 0; nt < 4; nt++)
                    mma8(acc[mt][nt], a[mt], b[nt]);
        }
        buf ^= 1;
    }

    // epilogue: bias + tf32 store into [B,H,T,HD]
    #pragma unroll
    for (int mt = 0; mt < 4; mt++) {
        int m0 = mbase + wm * 64 + mt * 16 + g;
        #pragma unroll
        for (int nt = 0; nt < 4; nt++) {
            int n0 = nloc + wn * 32 + nt * 8 + 2 * t4;
            int hh = n0 >> 6, d0 = n0 & 63;
            float bx = bias[n0], by = bias[n0 + 1];
            #pragma unroll
            for (int rr = 0; rr < 2; rr++) {
                int m = m0 + rr * 8;
                int bidx = m >> 11, t = m & (TT - 1);
                uint2 v;
                v.x = f2tf(acc[mt][nt][rr * 2 + 0] + bx);
                v.y = f2tf(acc[mt][nt][rr * 2 + 1] + by);
                *(uint2*)&out[(((size_t)(bidx * HH + hh) * TT) + t) * HD + d0] = v;
            }
        }
    }
}

// ---------------------------------------------------------------------------
// Flash attention, double-buffered K/V via cp.async, tf32 in/out.
// 128 threads = 4 warps; warp w owns q rows [qt*64+16w, +16).
// Dynamic smem: Ks[2][64][68] then Vs[2][64][72].
// ---------------------------------------------------------------------------
#define KS(s,r,c) smA[(s)*64*68 + (r)*68 + (c)]
#define VS(s,r,c) smV[(s)*64*72 + (r)*72 + (c)]

__global__ __launch_bounds__(128) void attn_tc2(const float* __restrict__ hbias)
{
    extern __shared__ unsigned smA[];
    unsigned* smV = smA + 2 * 64 * 68;

    int tid = threadIdx.x;
    int lane = tid & 31, warp = tid >> 5;
    int g = lane >> 2, t4 = lane & 3;

    int qt = (int)gridDim.x - 1 - (int)blockIdx.x;  // heavy tiles first
    int hh = blockIdx.y;
    int b  = blockIdx.z;
    int qbase = qt * 64;
    int qg0 = qbase + warp * 16 + g;
    int qg1 = qg0 + 8;

    const unsigned* qptr = g_q + (size_t)(b * HH + hh) * TT * HD;
    const unsigned* kptr = g_k + (size_t)(b * HH + hh) * TT * HD;
    const unsigned* vptr = g_v + (size_t)(b * HH + hh) * TT * HD;
    const float* hb0 = hbias + (size_t)(b * HH + hh) * TT * TT + (size_t)qg0 * TT;
    const float* hb1 = hb0 + (size_t)8 * TT;

    // Q fragments
    unsigned qa[8][4];
    #pragma unroll
    for (int d8 = 0; d8 < 8; d8++) {
        int dc = d8 * 8 + t4;
        qa[d8][0] = qptr[(size_t)qg0 * HD + dc];
        qa[d8][1] = qptr[(size_t)qg1 * HD + dc];
        qa[d8][2] = qptr[(size_t)qg0 * HD + dc + 4];
        qa[d8][3] = qptr[(size_t)qg1 * HD + dc + 4];
    }

    float m0 = -INFINITY, m1 = -INFINITY, l0 = 0.f, l1 = 0.f;
    float O[8][4];
    #pragma unroll
    for (int nt = 0; nt < 8; nt++)
        #pragma unroll
        for (int i = 0; i < 4; i++) O[nt][i] = 0.f;

    int ntiles = qt + 1;

    // prologue: stage 0 loads tile 0
    #pragma unroll
    for (int i = 0; i < 8; i++) {
        int idx = tid + i * 128;
        int row = idx >> 4, c4 = (idx & 15) * 4;
        cp16(&KS(0, row, c4), kptr + (size_t)row * HD + c4);
        cp16(&VS(0, row, c4), vptr + (size_t)row * HD + c4);
    }
    cp_commit();

    int buf = 0;
    for (int j = 0; j < ntiles; j++) {
        int kb = j * 64;
        cp_wait0();
        __syncthreads();
        if (j + 1 < ntiles) {
            int kn = (j + 1) * 64;
            #pragma unroll
            for (int i = 0; i < 8; i++) {
                int idx = tid + i * 128;
                int row = idx >> 4, c4 = (idx & 15) * 4;
                cp16(&KS(buf ^ 1, row, c4), kptr + (size_t)(kn + row) * HD + c4);
                cp16(&VS(buf ^ 1, row, c4), vptr + (size_t)(kn + row) * HD + c4);
            }
            cp_commit();
        }

        // prefetch h-bias for this tile into regs (LDG overlaps S mmas)
        float2 hA[8], hB[8];
        #pragma unroll
        for (int nt = 0; nt < 8; nt++) {
            int kg = kb + nt * 8 + 2 * t4;
            hA[nt] = *(const float2*)&hb0[kg];
            hB[nt] = *(const float2*)&hb1[kg];
        }

        // S = Q K^T
        float s[8][4];
        #pragma unroll
        for (int nt = 0; nt < 8; nt++) {
            s[nt][0] = s[nt][1] = s[nt][2] = s[nt][3] = 0.f;
            #pragma unroll
            for (int d8 = 0; d8 < 8; d8++) {
                int dc = d8 * 8 + t4;
                unsigned bb_[2];
                bb_[0] = KS(buf, nt * 8 + g, dc);
                bb_[1] = KS(buf, nt * 8 + g, dc + 4);
                mma8(s[nt], qa[d8], bb_);
            }
        }

        __syncthreads();   // all warps done reading Ks before P overwrites it

        // scale + bias + causal mask + row max
        float mt0 = -INFINITY, mt1 = -INFINITY;
        #pragma unroll
        for (int nt = 0; nt < 8; nt++) {
            int kg = kb + nt * 8 + 2 * t4;
            s[nt][0] = (kg     <= qg0) ? s[nt][0] * 0.125f + hA[nt].x : -INFINITY;
            s[nt][1] = (kg + 1 <= qg0) ? s[nt][1] * 0.125f + hA[nt].y : -INFINITY;
            s[nt][2] = (kg     <= qg1) ? s[nt][2] * 0.125f + hB[nt].x : -INFINITY;
            s[nt][3] = (kg + 1 <= qg1) ? s[nt][3] * 0.125f + hB[nt].y : -INFINITY;
            mt0 = fmaxf(mt0, fmaxf(s[nt][0], s[nt][1]));
            mt1 = fmaxf(mt1, fmaxf(s[nt][2], s[nt][3]));
        }
        mt0 = fmaxf(mt0, __shfl_xor_sync(0xffffffffu, mt0, 1));
        mt0 = fmaxf(mt0, __shfl_xor_sync(0xffffffffu, mt0, 2));
        mt1 = fmaxf(mt1, __shfl_xor_sync(0xffffffffu, mt1, 1));
        mt1 = fmaxf(mt1, __shfl_xor_sync(0xffffffffu, mt1, 2));

        float mn0 = fmaxf(m0, mt0), mn1 = fmaxf(m1, mt1);
        float al0 = __expf(m0 - mn0), al1 = __expf(m1 - mn1);
        float ls0 = 0.f, ls1 = 0.f;
        #pragma unroll
        for (int nt = 0; nt < 8; nt++) {
            s[nt][0] = __expf(s[nt][0] - mn0);
            s[nt][1] = __expf(s[nt][1] - mn0);
            s[nt][2] = __expf(s[nt][2] - mn1);
            s[nt][3] = __expf(s[nt][3] - mn1);
            ls0 += s[nt][0] + s[nt][1];
            ls1 += s[nt][2] + s[nt][3];
        }
        ls0 += __shfl_xor_sync(0xffffffffu, ls0, 1);
        ls0 += __shfl_xor_sync(0xffffffffu, ls0, 2);
        ls1 += __shfl_xor_sync(0xffffffffu, ls1, 1);
        ls1 += __shfl_xor_sync(0xffffffffu, ls1, 2);
        l0 = l0 * al0 + ls0;  m0 = mn0;
        l1 = l1 * al1 + ls1;  m1 = mn1;
        #pragma unroll
        for (int nt = 0; nt < 8; nt++) {
            O[nt][0] *= al0; O[nt][1] *= al0;
            O[nt][2] *= al1; O[nt][3] *= al1;
        }

        // P (tf32) into Ks[buf] rows [warp*16, +16) — own-warp rows only
        int pr0 = warp * 16 + g;
        #pragma unroll
        for (int nt = 0; nt < 8; nt++) {
            int c = nt * 8 + 2 * t4;
            KS(buf, pr0, c)         = f2tf(s[nt][0]);
            KS(buf, pr0, c + 1)     = f2tf(s[nt][1]);
            KS(buf, pr0 + 8, c)     = f2tf(s[nt][2]);
            KS(buf, pr0 + 8, c + 1) = f2tf(s[nt][3]);
        }
        __syncwarp();

        // O += P V
        #pragma unroll
        for (int k8 = 0; k8 < 8; k8++) {
            int kc = k8 * 8 + t4;
            unsigned ap[4];
            ap[0] = KS(buf, warp * 16 + g, kc);
            ap[1] = KS(buf, warp * 16 + g + 8, kc);
            ap[2] = KS(buf, warp * 16 + g, kc + 4);
            ap[3] = KS(buf, warp * 16 + g + 8, kc + 4);
            #pragma unroll
            for (int nt = 0; nt < 8; nt++) {
                unsigned bb_[2];
                bb_[0] = VS(buf, kc, nt * 8 + g);
                bb_[1] = VS(buf, kc + 4, nt * 8 + g);
                mma8(O[nt], ap, bb_);
            }
        }
        buf ^= 1;
    }

    float inv0 = 1.f / l0, inv1 = 1.f / l1;
    unsigned* y0 = g_y + ((size_t)b * TT + qg0) * CC + hh * HD;
    unsigned* y1 = g_y + ((size_t)b * TT + qg1) * CC + hh * HD;
    #pragma unroll
    for (int nt = 0; nt < 8; nt++) {
        int d = nt * 8 + 2 * t4;
        uint2 v0, v1;
        v0.x = f2tf(O[nt][0] * inv0); v0.y = f2tf(O[nt][1] * inv0);
        v1.x = f2tf(O[nt][2] * inv1); v1.y = f2tf(O[nt][3] * inv1);
        *(uint2*)&y0[d] = v0;
        *(uint2*)&y1[d] = v1;
    }
}

// ---------------------------------------------------------------------------
// Output projection, double-buffered cp.async: out = g_y @ Wp^T + bp (f32 out)
// ---------------------------------------------------------------------------
__global__ __launch_bounds__(256) void proj_gemm2(
    const float* __restrict__ bp, float* __restrict__ out)
{
    __shared__ unsigned As[2][128][20];
    __shared__ unsigned Bs[2][128][20];

    int tid = threadIdx.x;
    int lane = tid & 31, warp = tid >> 5;
    int g = lane >> 2, t4 = lane & 3;
    int wm = warp >> 2, wn = warp & 3;

    int mbase = blockIdx.y * 128;
    int nbase = blockIdx.x * 128;

    const unsigned* Ag = g_y + (size_t)mbase * CC;
    const unsigned* Bg = g_wpt + (size_t)nbase * CC;

    float acc[4][4][4];
    #pragma unroll
    for (int mt = 0; mt < 4; mt++)
        #pragma unroll
        for (int nt = 0; nt < 4; nt++)
            #pragma unroll
            for (int i = 0; i < 4; i++) acc[mt][nt][i] = 0.f;

    int lr = tid >> 2;
    int lc = (tid & 3) * 4;

    #pragma unroll
    for (int i = 0; i < 2; i++) {
        int row = lr + i * 64;
        cp16(&As[0][row][lc], Ag + (size_t)row * CC + lc);
        cp16(&Bs[0][row][lc], Bg + (size_t)row * CC + lc);
    }
    cp_commit();

    int buf = 0;
    for (int it = 0; it < 64; it++) {
        cp_wait0();
        __syncthreads();
        if (it < 63) {
            int k0 = (it + 1) * 16;
            #pragma unroll
            for (int i = 0; i < 2; i++) {
                int row = lr + i * 64;
                cp16(&As[buf ^ 1][row][lc], Ag + (size_t)row * CC + k0 + lc);
                cp16(&Bs[buf ^ 1][row][lc], Bg + (size_t)row * CC + k0 + lc);
            }
            cp_commit();
        }

        #pragma unroll
        for (int k8 = 0; k8 < 2; k8++) {
            int kc = k8 * 8 + t4;
            unsigned a[4][4], b[4][2];
            #pragma unroll
            for (int mt = 0; mt < 4; mt++) {
                int mr = wm * 64 + mt * 16 + g;
                a[mt][0] = As[buf][mr][kc];
                a[mt][1] = As[buf][mr + 8][kc];
                a[mt][2] = As[buf][mr][kc + 4];
                a[mt][3] = As[buf][mr + 8][kc + 4];
            }
            #pragma unroll
            for (int nt = 0; nt < 4; nt++) {
                int nr = wn * 32 + nt * 8 + g;
                b[nt][0] = Bs[buf][nr][kc];
                b[nt][1] = Bs[buf][nr][kc + 4];
            }
            #pragma unroll
            for (int mt = 0; mt < 4; mt++)
                #pragma unroll
                for (int nt = 0; nt < 4; nt++)
                    mma8(acc[mt][nt], a[mt], b[nt]);
        }
        buf ^= 1;
    }

    #pragma unroll
    for (int mt = 0; mt < 4; mt++) {
        int m0 = mbase + wm * 64 + mt * 16 + g;
        #pragma unroll
        for (int nt = 0; nt < 4; nt++) {
            int n0 = nbase + wn * 32 + nt * 8 + 2 * t4;
            float bx = bp[n0], by = bp[n0 + 1];
            #pragma unroll
            for (int rr = 0; rr < 2; rr++) {
                int m = m0 + rr * 8;
                float2 v;
                v.x = acc[mt][nt][rr * 2 + 0] + bx;
                v.y = acc[mt][nt][rr * 2 + 1] + by;
                *(float2*)&out[(size_t)m * CC + n0] = v;
            }
        }
    }
}

// ---------------------------------------------------------------------------
extern "C" void kernel_launch(void* const* d_in, const int* in_sizes, int n_in,
                              void* d_out, int out_size)
{
    const float* x  = (const float*)d_in[0];
    const float* h  = (const float*)d_in[1];
    const float* Wq = (const float*)d_in[2];
    const float* bq = (const float*)d_in[3];
    const float* Wk = (const float*)d_in[4];
    const float* bk = (const float*)d_in[5];
    const float* Wv = (const float*)d_in[6];
    const float* bv = (const float*)d_in[7];
    const float* Wp = (const float*)d_in[8];
    const float* bp = (const float*)d_in[9];
    float* out = (float*)d_out;

    static int smem_set = 0;
    const int attn_smem = (2 * 64 * 68 + 2 * 64 * 72) * 4;  // 71680 B
    if (!smem_set) {
        cudaFuncSetAttribute(attn_tc2, cudaFuncAttributeMaxDynamicSharedMemorySize,
                             attn_smem);
        smem_set = 1;
    }

    convert_tf32<<<8192, 256>>>(x, Wq, Wk, Wv, Wp);

    dim3 g1(24, 32);            // N=3072, M=4096 in 128x128 tiles
    qkv_gemm2<<<g1, 256>>>(bq, bk, bv);

    dim3 g2(TT / 64, HH, BB);   // 32 x 16 x 2
    attn_tc2<<<g2, 128, attn_smem>>>(h);

    dim3 g3(8, 32);             // N=1024, M=4096
    proj_gemm2<<<g3, 256>>>(bp, out);
}

// round 7
// speedup vs baseline: 1.2221x; 1.2221x over previous
#include <cuda_runtime.h>
#include <math.h>

#define BB 2
#define TT 2048
#define CC 1024
#define HH 16
#define HD 64

// Scratch (allocation-free rule: __device__ globals). tf32 bit patterns.
__device__ unsigned g_xt[4096*1024];     // x converted
__device__ unsigned g_wt[3072*1024];     // [Wq;Wk;Wv] converted
__device__ unsigned g_wpt[1024*1024];    // Wp converted
__device__ unsigned g_q[BB*HH*TT*HD];
__device__ unsigned g_k[BB*HH*TT*HD];
__device__ unsigned g_v[BB*HH*TT*HD];
__device__ unsigned g_y[BB*TT*CC];

// ---------------------------------------------------------------------------
// helpers
// ---------------------------------------------------------------------------
__device__ __forceinline__ unsigned f2tf(float f) {
    unsigned u;
    asm("cvt.rna.tf32.f32 %0, %1;" : "=r"(u) : "f"(f));
    return u;
}

__device__ __forceinline__ void mma8(float* c, const unsigned* a, const unsigned* b) {
    asm volatile(
        "mma.sync.aligned.m16n8k8.row.col.f32.tf32.tf32.f32 "
        "{%0,%1,%2,%3},{%4,%5,%6,%7},{%8,%9},{%0,%1,%2,%3};"
        : "+f"(c[0]), "+f"(c[1]), "+f"(c[2]), "+f"(c[3])
        : "r"(a[0]), "r"(a[1]), "r"(a[2]), "r"(a[3]), "r"(b[0]), "r"(b[1]));
}

__device__ __forceinline__ void cp16(void* dst_smem, const void* src) {
    unsigned d = (unsigned)__cvta_generic_to_shared(dst_smem);
    asm volatile("cp.async.cg.shared.global [%0], [%1], 16;\n" :: "r"(d), "l"(src));
}
__device__ __forceinline__ void cp_commit() {
    asm volatile("cp.async.commit_group;\n");
}
__device__ __forceinline__ void cp_wait0() {
    asm volatile("cp.async.wait_group 0;\n");
}

// ---------------------------------------------------------------------------
// Pre-convert x and weights to tf32 bits.
// ---------------------------------------------------------------------------
__global__ __launch_bounds__(256) void convert_tf32(
    const float* __restrict__ x,
    const float* __restrict__ Wq, const float* __restrict__ Wk,
    const float* __restrict__ Wv, const float* __restrict__ Wp)
{
    int i = blockIdx.x * 256 + threadIdx.x;   // float4 index
    const float* src; unsigned* dst; int off;
    if (i < 1048576)      { src = x;  dst = g_xt;            off = i; }
    else if (i < 1310720) { src = Wq; dst = g_wt;            off = i - 1048576; }
    else if (i < 1572864) { src = Wk; dst = g_wt + 1048576;  off = i - 1310720; }
    else if (i < 1835008) { src = Wv; dst = g_wt + 2097152;  off = i - 1572864; }
    else                  { src = Wp; dst = g_wpt;           off = i - 1835008; }
    float4 v = ((const float4*)src)[off];
    uint4 o;
    o.x = f2tf(v.x); o.y = f2tf(v.y); o.z = f2tf(v.z); o.w = f2tf(v.w);
    ((uint4*)dst)[off] = o;
}

// ---------------------------------------------------------------------------
// GEMM core: 128x128 tile, BK=32, 2-stage cp.async double buffer (dyn smem).
// 8 warps (2m x 4n), warp tile 64x32. A,B inputs are tf32 bits (K-major).
// Smem: As[2][128][36] then Bs[2][128][36]  (73728 bytes total)
// ---------------------------------------------------------------------------
#define AS(s,r,c) smem_[(s)*4608 + (r)*36 + (c)]
#define BS(s,r,c) smem_[9216 + (s)*4608 + (r)*36 + (c)]

struct GemmAcc { float a[4][4][4]; };

__device__ __forceinline__ void gemm_core(
    unsigned* smem_, const unsigned* Ag, const unsigned* Bg, GemmAcc& acc)
{
    int tid = threadIdx.x;
    int lane = tid & 31, warp = tid >> 5;
    int g = lane >> 2, t4 = lane & 3;
    int wm = warp >> 2, wn = warp & 3;

    #pragma unroll
    for (int mt = 0; mt < 4; mt++)
        #pragma unroll
        for (int nt = 0; nt < 4; nt++)
            #pragma unroll
            for (int i = 0; i < 4; i++) acc.a[mt][nt][i] = 0.f;

    // loader mapping: linear = tid + i*256 in [0,1024):
    //   row = linear>>3  (0..127), c4 = (linear&7)*4  (0,4,..,28)
    // prologue: stage 0 <- k0=0
    #pragma unroll
    for (int i = 0; i < 4; i++) {
        int linear = tid + i * 256;
        int row = linear >> 3, c4 = (linear & 7) * 4;
        cp16(&AS(0, row, c4), Ag + (size_t)row * CC + c4);
        cp16(&BS(0, row, c4), Bg + (size_t)row * CC + c4);
    }
    cp_commit();

    int buf = 0;
    for (int it = 0; it < 32; it++) {
        cp_wait0();
        __syncthreads();
        if (it < 31) {
            int k0 = (it + 1) * 32;
            #pragma unroll
            for (int i = 0; i < 4; i++) {
                int linear = tid + i * 256;
                int row = linear >> 3, c4 = (linear & 7) * 4;
                cp16(&AS(buf ^ 1, row, c4), Ag + (size_t)row * CC + k0 + c4);
                cp16(&BS(buf ^ 1, row, c4), Bg + (size_t)row * CC + k0 + c4);
            }
            cp_commit();
        }

        #pragma unroll
        for (int k8 = 0; k8 < 4; k8++) {
            int kc = k8 * 8 + t4;
            unsigned a[4][4], b[4][2];
            #pragma unroll
            for (int mt = 0; mt < 4; mt++) {
                int mr = wm * 64 + mt * 16 + g;
                a[mt][0] = AS(buf, mr, kc);
                a[mt][1] = AS(buf, mr + 8, kc);
                a[mt][2] = AS(buf, mr, kc + 4);
                a[mt][3] = AS(buf, mr + 8, kc + 4);
            }
            #pragma unroll
            for (int nt = 0; nt < 4; nt++) {
                int nr = wn * 32 + nt * 8 + g;
                b[nt][0] = BS(buf, nr, kc);
                b[nt][1] = BS(buf, nr, kc + 4);
            }
            #pragma unroll
            for (int mt = 0; mt < 4; mt++)
                #pragma unroll
                for (int nt = 0; nt < 4; nt++)
                    mma8(acc.a[mt][nt], a[mt], b[nt]);
        }
        buf ^= 1;
    }
}

// ---------------------------------------------------------------------------
// QKV projection -> tf32 bits in [B,H,T,HD]
// ---------------------------------------------------------------------------
__global__ __launch_bounds__(256) void qkv_gemm4(
    const float* __restrict__ bq, const float* __restrict__ bk,
    const float* __restrict__ bv)
{
    extern __shared__ unsigned smem_[];
    int tid = threadIdx.x;
    int lane = tid & 31, warp = tid >> 5;
    int g = lane >> 2, t4 = lane & 3;
    int wm = warp >> 2, wn = warp & 3;

    int mbase = blockIdx.y * 128;
    int cb = blockIdx.x * 128;
    int mat = cb >> 10;
    int nloc = cb & 1023;

    const float* bias = (mat == 0) ? bq : (mat == 1) ? bk : bv;
    unsigned* out     = (mat == 0) ? g_q : (mat == 1) ? g_k : g_v;

    GemmAcc acc;
    gemm_core(smem_, g_xt + (size_t)mbase * CC, g_wt + (size_t)cb * CC, acc);

    #pragma unroll
    for (int mt = 0; mt < 4; mt++) {
        int m0 = mbase + wm * 64 + mt * 16 + g;
        #pragma unroll
        for (int nt = 0; nt < 4; nt++) {
            int n0 = nloc + wn * 32 + nt * 8 + 2 * t4;
            int hh = n0 >> 6, d0 = n0 & 63;
            float bx = bias[n0], by = bias[n0 + 1];
            #pragma unroll
            for (int rr = 0; rr < 2; rr++) {
                int m = m0 + rr * 8;
                int bidx = m >> 11, t = m & (TT - 1);
                uint2 v;
                v.x = f2tf(acc.a[mt][nt][rr * 2 + 0] + bx);
                v.y = f2tf(acc.a[mt][nt][rr * 2 + 1] + by);
                *(uint2*)&out[(((size_t)(bidx * HH + hh) * TT) + t) * HD + d0] = v;
            }
        }
    }
}

// ---------------------------------------------------------------------------
// Output projection -> f32 out
// ---------------------------------------------------------------------------
__global__ __launch_bounds__(256) void proj_gemm4(
    const float* __restrict__ bp, float* __restrict__ out)
{
    extern __shared__ unsigned smem_[];
    int tid = threadIdx.x;
    int lane = tid & 31, warp = tid >> 5;
    int g = lane >> 2, t4 = lane & 3;
    int wm = warp >> 2, wn = warp & 3;

    int mbase = blockIdx.y * 128;
    int nbase = blockIdx.x * 128;

    GemmAcc acc;
    gemm_core(smem_, g_y + (size_t)mbase * CC, g_wpt + (size_t)nbase * CC, acc);

    #pragma unroll
    for (int mt = 0; mt < 4; mt++) {
        int m0 = mbase + wm * 64 + mt * 16 + g;
        #pragma unroll
        for (int nt = 0; nt < 4; nt++) {
            int n0 = nbase + wn * 32 + nt * 8 + 2 * t4;
            float bx = bp[n0], by = bp[n0 + 1];
            #pragma unroll
            for (int rr = 0; rr < 2; rr++) {
                int m = m0 + rr * 8;
                float2 v;
                v.x = acc.a[mt][nt][rr * 2 + 0] + bx;
                v.y = acc.a[mt][nt][rr * 2 + 1] + by;
                *(float2*)&out[(size_t)m * CC + n0] = v;
            }
        }
    }
}

// ---------------------------------------------------------------------------
// Flash attention (round-3 structure, tf32 scratch in/out).
// 128 threads = 4 warps; warp w owns q rows [qt*64+16w, +16).
// ---------------------------------------------------------------------------
__global__ __launch_bounds__(128) void attn_tc4(const float* __restrict__ hbias)
{
    __shared__ unsigned Ks[64][68];   // K tile, then reused for P
    __shared__ unsigned Vs[64][68];

    int tid = threadIdx.x;
    int lane = tid & 31, warp = tid >> 5;
    int g = lane >> 2, t4 = lane & 3;

    int qt = (int)gridDim.x - 1 - (int)blockIdx.x;  // heavy tiles first
    int hh = blockIdx.y;
    int b  = blockIdx.z;
    int qbase = qt * 64;
    int qg0 = qbase + warp * 16 + g;
    int qg1 = qg0 + 8;

    const unsigned* qptr = g_q + (size_t)(b * HH + hh) * TT * HD;
    const unsigned* kptr = g_k + (size_t)(b * HH + hh) * TT * HD;
    const unsigned* vptr = g_v + (size_t)(b * HH + hh) * TT * HD;
    const float* hb0 = hbias + (size_t)(b * HH + hh) * TT * TT + (size_t)qg0 * TT;
    const float* hb1 = hb0 + (size_t)8 * TT;

    unsigned qa[8][4];
    #pragma unroll
    for (int d8 = 0; d8 < 8; d8++) {
        int dc = d8 * 8 + t4;
        qa[d8][0] = qptr[(size_t)qg0 * HD + dc];
        qa[d8][1] = qptr[(size_t)qg1 * HD + dc];
        qa[d8][2] = qptr[(size_t)qg0 * HD + dc + 4];
        qa[d8][3] = qptr[(size_t)qg1 * HD + dc + 4];
    }

    float m0 = -INFINITY, m1 = -INFINITY, l0 = 0.f, l1 = 0.f;
    float O[8][4];
    #pragma unroll
    for (int nt = 0; nt < 8; nt++)
        #pragma unroll
        for (int i = 0; i < 4; i++) O[nt][i] = 0.f;

    int ntiles = qt + 1;
    for (int j = 0; j < ntiles; j++) {
        int kb = j * 64;
        __syncthreads();   // prior PV reads of Ks/Vs done
        #pragma unroll
        for (int i = 0; i < 8; i++) {
            int idx = tid + i * 128;
            int row = idx >> 4, c4 = (idx & 15) * 4;
            *(uint4*)&Ks[row][c4] = *(const uint4*)&kptr[(size_t)(kb + row) * HD + c4];
            *(uint4*)&Vs[row][c4] = *(const uint4*)&vptr[(size_t)(kb + row) * HD + c4];
        }
        __syncthreads();

        // prefetch h-bias for this tile into regs
        float2 hA[8], hB[8];
        #pragma unroll
        for (int nt = 0; nt < 8; nt++) {
            int kg = kb + nt * 8 + 2 * t4;
            hA[nt] = *(const float2*)&hb0[kg];
            hB[nt] = *(const float2*)&hb1[kg];
        }

        // S = Q K^T
        float s[8][4];
        #pragma unroll
        for (int nt = 0; nt < 8; nt++) {
            s[nt][0] = s[nt][1] = s[nt][2] = s[nt][3] = 0.f;
            #pragma unroll
            for (int d8 = 0; d8 < 8; d8++) {
                int dc = d8 * 8 + t4;
                unsigned bb_[2];
                bb_[0] = Ks[nt * 8 + g][dc];
                bb_[1] = Ks[nt * 8 + g][dc + 4];
                mma8(s[nt], qa[d8], bb_);
            }
        }

        __syncthreads();   // all warps done reading Ks before P overwrites it

        float mt0 = -INFINITY, mt1 = -INFINITY;
        #pragma unroll
        for (int nt = 0; nt < 8; nt++) {
            int kg = kb + nt * 8 + 2 * t4;
            s[nt][0] = (kg     <= qg0) ? s[nt][0] * 0.125f + hA[nt].x : -INFINITY;
            s[nt][1] = (kg + 1 <= qg0) ? s[nt][1] * 0.125f + hA[nt].y : -INFINITY;
            s[nt][2] = (kg     <= qg1) ? s[nt][2] * 0.125f + hB[nt].x : -INFINITY;
            s[nt][3] = (kg + 1 <= qg1) ? s[nt][3] * 0.125f + hB[nt].y : -INFINITY;
            mt0 = fmaxf(mt0, fmaxf(s[nt][0], s[nt][1]));
            mt1 = fmaxf(mt1, fmaxf(s[nt][2], s[nt][3]));
        }
        mt0 = fmaxf(mt0, __shfl_xor_sync(0xffffffffu, mt0, 1));
        mt0 = fmaxf(mt0, __shfl_xor_sync(0xffffffffu, mt0, 2));
        mt1 = fmaxf(mt1, __shfl_xor_sync(0xffffffffu, mt1, 1));
        mt1 = fmaxf(mt1, __shfl_xor_sync(0xffffffffu, mt1, 2));

        float mn0 = fmaxf(m0, mt0), mn1 = fmaxf(m1, mt1);
        float al0 = __expf(m0 - mn0), al1 = __expf(m1 - mn1);
        float ls0 = 0.f, ls1 = 0.f;
        #pragma unroll
        for (int nt = 0; nt < 8; nt++) {
            s[nt][0] = __expf(s[nt][0] - mn0);
            s[nt][1] = __expf(s[nt][1] - mn0);
            s[nt][2] = __expf(s[nt][2] - mn1);
            s[nt][3] = __expf(s[nt][3] - mn1);
            ls0 += s[nt][0] + s[nt][1];
            ls1 += s[nt][2] + s[nt][3];
        }
        ls0 += __shfl_xor_sync(0xffffffffu, ls0, 1);
        ls0 += __shfl_xor_sync(0xffffffffu, ls0, 2);
        ls1 += __shfl_xor_sync(0xffffffffu, ls1, 1);
        ls1 += __shfl_xor_sync(0xffffffffu, ls1, 2);
        l0 = l0 * al0 + ls0;  m0 = mn0;
        l1 = l1 * al1 + ls1;  m1 = mn1;
        #pragma unroll
        for (int nt = 0; nt < 8; nt++) {
            O[nt][0] *= al0; O[nt][1] *= al0;
            O[nt][2] *= al1; O[nt][3] *= al1;
        }

        int pr0 = warp * 16 + g;
        #pragma unroll
        for (int nt = 0; nt < 8; nt++) {
            int c = nt * 8 + 2 * t4;
            Ks[pr0][c]         = f2tf(s[nt][0]);
            Ks[pr0][c + 1]     = f2tf(s[nt][1]);
            Ks[pr0 + 8][c]     = f2tf(s[nt][2]);
            Ks[pr0 + 8][c + 1] = f2tf(s[nt][3]);
        }
        __syncwarp();

        // O += P V
        #pragma unroll
        for (int k8 = 0; k8 < 8; k8++) {
            int kc = k8 * 8 + t4;
            unsigned ap[4];
            ap[0] = Ks[warp * 16 + g][kc];
            ap[1] = Ks[warp * 16 + g + 8][kc];
            ap[2] = Ks[warp * 16 + g][kc + 4];
            ap[3] = Ks[warp * 16 + g + 8][kc + 4];
            #pragma unroll
            for (int nt = 0; nt < 8; nt++) {
                unsigned bb_[2];
                bb_[0] = Vs[kc][nt * 8 + g];
                bb_[1] = Vs[kc + 4][nt * 8 + g];
                mma8(O[nt], ap, bb_);
            }
        }
    }

    float inv0 = 1.f / l0, inv1 = 1.f / l1;
    unsigned* y0 = g_y + ((size_t)b * TT + qg0) * CC + hh * HD;
    unsigned* y1 = g_y + ((size_t)b * TT + qg1) * CC + hh * HD;
    #pragma unroll
    for (int nt = 0; nt < 8; nt++) {
        int d = nt * 8 + 2 * t4;
        uint2 v0, v1;
        v0.x = f2tf(O[nt][0] * inv0); v0.y = f2tf(O[nt][1] * inv0);
        v1.x = f2tf(O[nt][2] * inv1); v1.y = f2tf(O[nt][3] * inv1);
        *(uint2*)&y0[d] = v0;
        *(uint2*)&y1[d] = v1;
    }
}

// ---------------------------------------------------------------------------
extern "C" void kernel_launch(void* const* d_in, const int* in_sizes, int n_in,
                              void* d_out, int out_size)
{
    const float* x  = (const float*)d_in[0];
    const float* h  = (const float*)d_in[1];
    const float* Wq = (const float*)d_in[2];
    const float* bq = (const float*)d_in[3];
    const float* Wk = (const float*)d_in[4];
    const float* bk = (const float*)d_in[5];
    const float* Wv = (const float*)d_in[6];
    const float* bv = (const float*)d_in[7];
    const float* Wp = (const float*)d_in[8];
    const float* bp = (const float*)d_in[9];
    float* out = (float*)d_out;

    const int gemm_smem = 2 * (128 * 36 + 128 * 36) * 4;  // 73728 B
    static int smem_set = 0;
    if (!smem_set) {
        cudaFuncSetAttribute(qkv_gemm4, cudaFuncAttributeMaxDynamicSharedMemorySize,
                             gemm_smem);
        cudaFuncSetAttribute(proj_gemm4, cudaFuncAttributeMaxDynamicSharedMemorySize,
                             gemm_smem);
        smem_set = 1;
    }

    convert_tf32<<<8192, 256>>>(x, Wq, Wk, Wv, Wp);

    dim3 g1(24, 32);            // N=3072, M=4096 in 128x128 tiles
    qkv_gemm4<<<g1, 256, gemm_smem>>>(bq, bk, bv);

    dim3 g2(TT / 64, HH, BB);   // 32 x 16 x 2
    attn_tc4<<<g2, 128>>>(h);

    dim3 g3(8, 32);             // N=1024, M=4096
    proj_gemm4<<<g3, 256, gemm_smem>>>(bp, out);
}

// round 9
// speedup vs baseline: 2.1337x; 1.7460x over previous
#include <cuda_runtime.h>
#include <cuda_fp16.h>
#include <math.h>

#define BB 2
#define TT 2048
#define CC 1024
#define HH 16
#define HD 64

// Scratch (allocation-free rule: __device__ globals). fp16.
__device__ __half g_xt[4096*1024];     // x converted
__device__ __half g_wt[3072*1024];     // [Wq;Wk;Wv] converted
__device__ __half g_wpt[1024*1024];    // Wp converted
__device__ __half g_q[BB*HH*TT*HD];
__device__ __half g_k[BB*HH*TT*HD];
__device__ __half g_v[BB*HH*TT*HD];
__device__ __half g_y[BB*TT*CC];

// ---------------------------------------------------------------------------
// helpers
// ---------------------------------------------------------------------------
__device__ __forceinline__ void mma16(float* c, const unsigned* a, const unsigned* b) {
    asm volatile(
        "mma.sync.aligned.m16n8k16.row.col.f32.f16.f16.f32 "
        "{%0,%1,%2,%3},{%4,%5,%6,%7},{%8,%9},{%0,%1,%2,%3};"
        : "+f"(c[0]), "+f"(c[1]), "+f"(c[2]), "+f"(c[3])
        : "r"(a[0]), "r"(a[1]), "r"(a[2]), "r"(a[3]), "r"(b[0]), "r"(b[1]));
}

__device__ __forceinline__ void ldsm4(unsigned& d0, unsigned& d1, unsigned& d2,
                                      unsigned& d3, unsigned addr) {
    asm volatile("ldmatrix.sync.aligned.m8n8.x4.shared.b16 {%0,%1,%2,%3}, [%4];"
                 : "=r"(d0), "=r"(d1), "=r"(d2), "=r"(d3) : "r"(addr));
}
__device__ __forceinline__ void ldsm4t(unsigned& d0, unsigned& d1, unsigned& d2,
                                       unsigned& d3, unsigned addr) {
    asm volatile("ldmatrix.sync.aligned.m8n8.x4.trans.shared.b16 {%0,%1,%2,%3}, [%4];"
                 : "=r"(d0), "=r"(d1), "=r"(d2), "=r"(d3) : "r"(addr));
}

__device__ __forceinline__ void cp16(void* dst_smem, const void* src) {
    unsigned d = (unsigned)__cvta_generic_to_shared(dst_smem);
    asm volatile("cp.async.cg.shared.global [%0], [%1], 16;\n" :: "r"(d), "l"(src));
}
__device__ __forceinline__ void cp_commit() {
    asm volatile("cp.async.commit_group;\n");
}
__device__ __forceinline__ void cp_wait0() {
    asm volatile("cp.async.wait_group 0;\n");
}

// ---------------------------------------------------------------------------
// Pre-convert x and weights to fp16.
// ---------------------------------------------------------------------------
__global__ __launch_bounds__(256) void convert_fp16(
    const float* __restrict__ x,
    const float* __restrict__ Wq, const float* __restrict__ Wk,
    const float* __restrict__ Wv, const float* __restrict__ Wp)
{
    int i = blockIdx.x * 256 + threadIdx.x;   // float4 index
    if (i >= 2097152) return;
    const float* src; __half* dst; int off;
    if (i < 1048576)      { src = x;  dst = g_xt;            off = i; }
    else if (i < 1310720) { src = Wq; dst = g_wt;            off = i - 1048576; }
    else if (i < 1572864) { src = Wk; dst = g_wt + 1048576;  off = i - 1310720; }
    else if (i < 1835008) { src = Wv; dst = g_wt + 2097152;  off = i - 1572864; }
    else                  { src = Wp; dst = g_wpt;           off = i - 1835008; }
    float4 v = ((const float4*)src)[off];
    __half2 lo = __floats2half2_rn(v.x, v.y);
    __half2 hi = __floats2half2_rn(v.z, v.w);
    uint2 o;
    o.x = *(unsigned*)&lo;
    o.y = *(unsigned*)&hi;
    ((uint2*)dst)[off] = o;
}

// ---------------------------------------------------------------------------
// GEMM core: 128x128 tile, BK=64 (halfs), 2-stage cp.async double buffer.
// 8 warps (2m x 4n), warp tile 64x32. m16n8k16 fp16 mma, ldmatrix loads.
// Smem halfs, row stride 72 (144B -> conflict-free ldmatrix).
//   A: stages at byte 0 and 18432;  B: 36864 + stage*18432. Total 73728 B.
// ---------------------------------------------------------------------------
struct GemmAcc { float a[4][4][4]; };

__device__ __forceinline__ void gemm_core(
    __half* smh, const __half* Ag, const __half* Bg, GemmAcc& acc)
{
    int tid = threadIdx.x;
    int lane = tid & 31, warp = tid >> 5;
    int wm = warp >> 2, wn = warp & 3;

    #pragma unroll
    for (int mt = 0; mt < 4; mt++)
        #pragma unroll
        for (int nt = 0; nt < 4; nt++)
            #pragma unroll
            for (int i = 0; i < 4; i++) acc.a[mt][nt][i] = 0.f;

    unsigned sbase = (unsigned)__cvta_generic_to_shared(smh);

    // ldmatrix byte offsets (within a stage), kb term added in loop
    unsigned a_off[4];
    #pragma unroll
    for (int mt = 0; mt < 4; mt++)
        a_off[mt] = (unsigned)((wm * 64 + mt * 16 + (lane & 15)) * 144
                               + (lane >> 4) * 16);
    unsigned b_off[2];
    #pragma unroll
    for (int np = 0; np < 2; np++) {
        int row = wn * 32 + np * 16 + ((lane >> 4) * 8) + (lane & 7);
        b_off[np] = (unsigned)(36864 + row * 144 + ((lane >> 3) & 1) * 16);
    }

    // loader: per stage, A and B each 1024 16B-chunks / 256 thr = 4 each
    // linear = tid + i*256: row = linear>>3 (0..127), c16 = linear&7
    // prologue: stage 0, k0 = 0
    #pragma unroll
    for (int i = 0; i < 4; i++) {
        int linear = tid + i * 256;
        int row = linear >> 3, c16 = linear & 7;
        cp16(smh + row * 72 + c16 * 8, Ag + (size_t)row * CC + c16 * 8);
        cp16(smh + 18432 + row * 72 + c16 * 8, Bg + (size_t)row * CC + c16 * 8);
    }
    cp_commit();

    int buf = 0;
    for (int it = 0; it < 16; it++) {
        cp_wait0();
        __syncthreads();
        if (it < 15) {
            int k0 = (it + 1) * 64;
            int so = (buf ^ 1) * 9216;   // stage offset in halfs
            #pragma unroll
            for (int i = 0; i < 4; i++) {
                int linear = tid + i * 256;
                int row = linear >> 3, c16 = linear & 7;
                cp16(smh + so + row * 72 + c16 * 8,
                     Ag + (size_t)row * CC + k0 + c16 * 8);
                cp16(smh + 18432 + so + row * 72 + c16 * 8,
                     Bg + (size_t)row * CC + k0 + c16 * 8);
            }
            cp_commit();
        }

        unsigned stage_b = buf * 18432;   // bytes
        #pragma unroll
        for (int kk = 0; kk < 4; kk++) {
            unsigned kbb = stage_b + kk * 32;
            unsigned a[4][4], b[4][2];
            #pragma unroll
            for (int mt = 0; mt < 4; mt++)
                ldsm4(a[mt][0], a[mt][1], a[mt][2], a[mt][3],
                      sbase + a_off[mt] + kbb);
            #pragma unroll
            for (int np = 0; np < 2; np++)
                ldsm4(b[2*np][0], b[2*np][1], b[2*np+1][0], b[2*np+1][1],
                      sbase + b_off[np] + kbb);
            #pragma unroll
            for (int mt = 0; mt < 4; mt++)
                #pragma unroll
                for (int nt = 0; nt < 4; nt++)
                    mma16(acc.a[mt][nt], a[mt], b[nt]);
        }
        buf ^= 1;
    }
}

// ---------------------------------------------------------------------------
// QKV projection -> fp16 in [B,H,T,HD]
// ---------------------------------------------------------------------------
__global__ __launch_bounds__(256) void qkv_gemm5(
    const float* __restrict__ bq, const float* __restrict__ bk,
    const float* __restrict__ bv)
{
    extern __shared__ __half smh[];
    int tid = threadIdx.x;
    int lane = tid & 31, warp = tid >> 5;
    int g = lane >> 2, t4 = lane & 3;
    int wm = warp >> 2, wn = warp & 3;

    int mbase = blockIdx.y * 128;
    int cb = blockIdx.x * 128;
    int mat = cb >> 10;
    int nloc = cb & 1023;

    const float* bias = (mat == 0) ? bq : (mat == 1) ? bk : bv;
    __half* out       = (mat == 0) ? g_q : (mat == 1) ? g_k : g_v;

    GemmAcc acc;
    gemm_core(smh, g_xt + (size_t)mbase * CC, g_wt + (size_t)cb * CC, acc);

    #pragma unroll
    for (int mt = 0; mt < 4; mt++) {
        int m0 = mbase + wm * 64 + mt * 16 + g;
        #pragma unroll
        for (int nt = 0; nt < 4; nt++) {
            int n0 = nloc + wn * 32 + nt * 8 + 2 * t4;
            int hh = n0 >> 6, d0 = n0 & 63;
            float bx = bias[n0], by = bias[n0 + 1];
            #pragma unroll
            for (int rr = 0; rr < 2; rr++) {
                int m = m0 + rr * 8;
                int bidx = m >> 11, t = m & (TT - 1);
                __half2 v = __floats2half2_rn(acc.a[mt][nt][rr * 2 + 0] + bx,
                                              acc.a[mt][nt][rr * 2 + 1] + by);
                *(__half2*)&out[(((size_t)(bidx * HH + hh) * TT) + t) * HD + d0] = v;
            }
        }
    }
}

// ---------------------------------------------------------------------------
// Output projection -> f32 out
// ---------------------------------------------------------------------------
__global__ __launch_bounds__(256) void proj_gemm5(
    const float* __restrict__ bp, float* __restrict__ out)
{
    extern __shared__ __half smh[];
    int tid = threadIdx.x;
    int lane = tid & 31, warp = tid >> 5;
    int g = lane >> 2, t4 = lane & 3;
    int wm = warp >> 2, wn = warp & 3;

    int mbase = blockIdx.y * 128;
    int nbase = blockIdx.x * 128;

    GemmAcc acc;
    gemm_core(smh, g_y + (size_t)mbase * CC, g_wpt + (size_t)nbase * CC, acc);

    #pragma unroll
    for (int mt = 0; mt < 4; mt++) {
        int m0 = mbase + wm * 64 + mt * 16 + g;
        #pragma unroll
        for (int nt = 0; nt < 4; nt++) {
            int n0 = nbase + wn * 32 + nt * 8 + 2 * t4;
            float bx = bp[n0], by = bp[n0 + 1];
            #pragma unroll
            for (int rr = 0; rr < 2; rr++) {
                int m = m0 + rr * 8;
                float2 v;
                v.x = acc.a[mt][nt][rr * 2 + 0] + bx;
                v.y = acc.a[mt][nt][rr * 2 + 1] + by;
                *(float2*)&out[(size_t)m * CC + n0] = v;
            }
        }
    }
}

// ---------------------------------------------------------------------------
// Flash attention, fp16 fragments via ldmatrix. 128 threads = 4 warps; warp w
// owns q rows [qt*64+16w, +16). Q-frags in regs; P reuses K smem buffer.
// Smem rows: 72 halfs (144B stride, conflict-free ldmatrix).
// ---------------------------------------------------------------------------
__global__ __launch_bounds__(128) void attn_tc5(const float* __restrict__ hbias)
{
    __shared__ __half Ks[64][72];   // K tile, then reused for P (fp16)
    __shared__ __half Vs[64][72];

    int tid = threadIdx.x;
    int lane = tid & 31, warp = tid >> 5;
    int g = lane >> 2, t4 = lane & 3;

    int qt = (int)gridDim.x - 1 - (int)blockIdx.x;  // heavy tiles first
    int hh = blockIdx.y;
    int b  = blockIdx.z;
    int qbase = qt * 64;
    int qg0 = qbase + warp * 16 + g;
    int qg1 = qg0 + 8;

    const __half* qptr = g_q + (size_t)(b * HH + hh) * TT * HD;
    const __half* kptr = g_k + (size_t)(b * HH + hh) * TT * HD;
    const __half* vptr = g_v + (size_t)(b * HH + hh) * TT * HD;
    const float* hb0 = hbias + (size_t)(b * HH + hh) * TT * TT + (size_t)qg0 * TT;
    const float* hb1 = hb0 + (size_t)8 * TT;

    unsigned ks_base = (unsigned)__cvta_generic_to_shared(&Ks[0][0]);
    unsigned vs_base = (unsigned)__cvta_generic_to_shared(&Vs[0][0]);

    // ldmatrix offsets
    unsigned k_off[4];     // S-phase B: np covers nt pair
    #pragma unroll
    for (int np = 0; np < 4; np++) {
        int row = np * 16 + ((lane >> 4) * 8) + (lane & 7);
        k_off[np] = (unsigned)(row * 144 + ((lane >> 3) & 1) * 16);
    }
    unsigned p_off = (unsigned)((warp * 16 + (lane & 15)) * 144 + (lane >> 4) * 16);
    unsigned v_off[4];     // PV-phase B (trans): np covers d pair
    #pragma unroll
    for (int np = 0; np < 4; np++)
        v_off[np] = (unsigned)((lane & 15) * 144 + (np * 16 + (lane >> 4) * 8) * 2);

    // Q fragments: [kk][4], kk = k16 step over HD
    unsigned qa[4][4];
    #pragma unroll
    for (int kk = 0; kk < 4; kk++) {
        int dc = kk * 16 + 2 * t4;
        qa[kk][0] = *(const unsigned*)(qptr + (size_t)qg0 * HD + dc);
        qa[kk][1] = *(const unsigned*)(qptr + (size_t)qg1 * HD + dc);
        qa[kk][2] = *(const unsigned*)(qptr + (size_t)qg0 * HD + dc + 8);
        qa[kk][3] = *(const unsigned*)(qptr + (size_t)qg1 * HD + dc + 8);
    }

    float m0 = -INFINITY, m1 = -INFINITY, l0 = 0.f, l1 = 0.f;
    float O[8][4];
    #pragma unroll
    for (int nt = 0; nt < 8; nt++)
        #pragma unroll
        for (int i = 0; i < 4; i++) O[nt][i] = 0.f;

    int ntiles = qt + 1;
    for (int j = 0; j < ntiles; j++) {
        int kb = j * 64;
        __syncthreads();   // prior PV reads of Ks/Vs done
        #pragma unroll
        for (int i = 0; i < 4; i++) {
            int idx = tid + i * 128;
            int row = idx >> 3, c16 = idx & 7;
            *(uint4*)&Ks[row][c16 * 8] =
                *(const uint4*)(kptr + (size_t)(kb + row) * HD + c16 * 8);
            *(uint4*)&Vs[row][c16 * 8] =
                *(const uint4*)(vptr + (size_t)(kb + row) * HD + c16 * 8);
        }
        __syncthreads();

        // prefetch h-bias into regs
        float2 hA[8], hB[8];
        #pragma unroll
        for (int nt = 0; nt < 8; nt++) {
            int kg = kb + nt * 8 + 2 * t4;
            hA[nt] = *(const float2*)&hb0[kg];
            hB[nt] = *(const float2*)&hb1[kg];
        }

        // S = Q K^T
        float s[8][4];
        #pragma unroll
        for (int nt = 0; nt < 8; nt++)
            s[nt][0] = s[nt][1] = s[nt][2] = s[nt][3] = 0.f;
        #pragma unroll
        for (int kk = 0; kk < 4; kk++) {
            unsigned bfr[8][2];
            #pragma unroll
            for (int np = 0; np < 4; np++)
                ldsm4(bfr[2*np][0], bfr[2*np][1], bfr[2*np+1][0], bfr[2*np+1][1],
                      ks_base + k_off[np] + kk * 32);
            #pragma unroll
            for (int nt = 0; nt < 8; nt++)
                mma16(s[nt], qa[kk], bfr[nt]);
        }

        __syncthreads();   // all warps done reading Ks before P overwrites it

        float mt0 = -INFINITY, mt1 = -INFINITY;
        #pragma unroll
        for (int nt = 0; nt < 8; nt++) {
            int kg = kb + nt * 8 + 2 * t4;
            s[nt][0] = (kg     <= qg0) ? s[nt][0] * 0.125f + hA[nt].x : -INFINITY;
            s[nt][1] = (kg + 1 <= qg0) ? s[nt][1] * 0.125f + hA[nt].y : -INFINITY;
            s[nt][2] = (kg     <= qg1) ? s[nt][2] * 0.125f + hB[nt].x : -INFINITY;
            s[nt][3] = (kg + 1 <= qg1) ? s[nt][3] * 0.125f + hB[nt].y : -INFINITY;
            mt0 = fmaxf(mt0, fmaxf(s[nt][0], s[nt][1]));
            mt1 = fmaxf(mt1, fmaxf(s[nt][2], s[nt][3]));
        }
        mt0 = fmaxf(mt0, __shfl_xor_sync(0xffffffffu, mt0, 1));
        mt0 = fmaxf(mt0, __shfl_xor_sync(0xffffffffu, mt0, 2));
        mt1 = fmaxf(mt1, __shfl_xor_sync(0xffffffffu, mt1, 1));
        mt1 = fmaxf(mt1, __shfl_xor_sync(0xffffffffu, mt1, 2));

        float mn0 = fmaxf(m0, mt0), mn1 = fmaxf(m1, mt1);
        float al0 = __expf(m0 - mn0), al1 = __expf(m1 - mn1);
        float ls0 = 0.f, ls1 = 0.f;
        #pragma unroll
        for (int nt = 0; nt < 8; nt++) {
            s[nt][0] = __expf(s[nt][0] - mn0);
            s[nt][1] = __expf(s[nt][1] - mn0);
            s[nt][2] = __expf(s[nt][2] - mn1);
            s[nt][3] = __expf(s[nt][3] - mn1);
            ls0 += s[nt][0] + s[nt][1];
            ls1 += s[nt][2] + s[nt][3];
        }
        ls0 += __shfl_xor_sync(0xffffffffu, ls0, 1);
        ls0 += __shfl_xor_sync(0xffffffffu, ls0, 2);
        ls1 += __shfl_xor_sync(0xffffffffu, ls1, 1);
        ls1 += __shfl_xor_sync(0xffffffffu, ls1, 2);
        l0 = l0 * al0 + ls0;  m0 = mn0;
        l1 = l1 * al1 + ls1;  m1 = mn1;
        #pragma unroll
        for (int nt = 0; nt < 8; nt++) {
            O[nt][0] *= al0; O[nt][1] *= al0;
            O[nt][2] *= al1; O[nt][3] *= al1;
        }

        // P (fp16) into own-warp Ks rows
        int pr0 = warp * 16 + g;
        #pragma unroll
        for (int nt = 0; nt < 8; nt++) {
            int c = nt * 8 + 2 * t4;
            *(__half2*)&Ks[pr0][c]     = __floats2half2_rn(s[nt][0], s[nt][1]);
            *(__half2*)&Ks[pr0 + 8][c] = __floats2half2_rn(s[nt][2], s[nt][3]);
        }
        __syncwarp();

        // O += P V   (A = P via ldmatrix, B = V^T via ldmatrix.trans)
        #pragma unroll
        for (int kk = 0; kk < 4; kk++) {
            unsigned ap[4];
            ldsm4(ap[0], ap[1], ap[2], ap[3], ks_base + p_off + kk * 32);
            unsigned bv_[8][2];
            #pragma unroll
            for (int np = 0; np < 4; np++)
                ldsm4t(bv_[2*np][0], bv_[2*np][1], bv_[2*np+1][0], bv_[2*np+1][1],
                       vs_base + v_off[np] + kk * 2304);
            #pragma unroll
            for (int nt = 0; nt < 8; nt++)
                mma16(O[nt], ap, bv_[nt]);
        }
    }

    float inv0 = 1.f / l0, inv1 = 1.f / l1;
    __half* y0 = g_y + ((size_t)b * TT + qg0) * CC + hh * HD;
    __half* y1 = g_y + ((size_t)b * TT + qg1) * CC + hh * HD;
    #pragma unroll
    for (int nt = 0; nt < 8; nt++) {
        int d = nt * 8 + 2 * t4;
        *(__half2*)&y0[d] = __floats2half2_rn(O[nt][0] * inv0, O[nt][1] * inv0);
        *(__half2*)&y1[d] = __floats2half2_rn(O[nt][2] * inv1, O[nt][3] * inv1);
    }
}

// ---------------------------------------------------------------------------
extern "C" void kernel_launch(void* const* d_in, const int* in_sizes, int n_in,
                              void* d_out, int out_size)
{
    const float* x  = (const float*)d_in[0];
    const float* h  = (const float*)d_in[1];
    const float* Wq = (const float*)d_in[2];
    const float* bq = (const float*)d_in[3];
    const float* Wk = (const float*)d_in[4];
    const float* bk = (const float*)d_in[5];
    const float* Wv = (const float*)d_in[6];
    const float* bv = (const float*)d_in[7];
    const float* Wp = (const float*)d_in[8];
    const float* bp = (const float*)d_in[9];
    float* out = (float*)d_out;

    const int gemm_smem = 73728;   // 2 stages * (A 18432B + B 18432B)
    static int smem_set = 0;
    if (!smem_set) {
        cudaFuncSetAttribute(qkv_gemm5, cudaFuncAttributeMaxDynamicSharedMemorySize,
                             gemm_smem);
        cudaFuncSetAttribute(proj_gemm5, cudaFuncAttributeMaxDynamicSharedMemorySize,
                             gemm_smem);
        smem_set = 1;
    }

    convert_fp16<<<8192, 256>>>(x, Wq, Wk, Wv, Wp);

    dim3 g1(24, 32);            // N=3072, M=4096 in 128x128 tiles
    qkv_gemm5<<<g1, 256, gemm_smem>>>(bq, bk, bv);

    dim3 g2(TT / 64, HH, BB);   // 32 x 16 x 2
    attn_tc5<<<g2, 128>>>(h);

    dim3 g3(8, 32);             // N=1024, M=4096
    proj_gemm5<<<g3, 256, gemm_smem>>>(bp, out);
}